// round 11
// baseline (speedup 1.0000x reference)
#include <cuda_runtime.h>

// cumprod along dim 1 of a (4096, 8192) fp32 matrix.
// CTA-per-row, 256 threads = 8 warps; warp w owns floats [1024w, 1024w+1024),
// lane L owns float4 L of each 128-float chunk (LDG/STG.128 coalesced).
// TWO-PASS / LOW-REGISTER variant: pass 1 streams the segment from DRAM
// (default policy -> lines stay in L2; per-wave footprint ~23MB << 126MB L2)
// computing only the order-independent segment total. Pass 2 re-reads the
// same lines from L2 (__ldcs, evict-after-use) through a depth-4 ring whose
// prologue is issued BEFORE the barrier, then scans, scales by the global
// prefix, and stores. ~36 regs -> 7 CTAs/SM instead of 5.

#define ROW_LEN  8192
#define THREADS  256
#define NWARPS   8
#define CHUNKS   8                    // 128-float chunks per warp segment
#define SEG_VEC  256                  // float4 per warp segment
#define DEPTH    4                    // pass-2 reload ring depth

__global__ void __launch_bounds__(THREADS, 7)
cumprod_dim1_kernel(const float* __restrict__ x, float* __restrict__ y) {
    __shared__ float wtot[NWARPS];

    const int t    = threadIdx.x;
    const int lane = t & 31;
    const int w    = t >> 5;

    const size_t row_off = (size_t)blockIdx.x * ROW_LEN;
    const float4* __restrict__ xin  = reinterpret_cast<const float4*>(x + row_off);
    float4* __restrict__       yout = reinterpret_cast<float4*>(y + row_off);

    const int segl = w * SEG_VEC + lane;   // lane's float4 slot in chunk 0

    // ---- pass 1: stream segment, accumulate order-independent total ----
    // (two batches of 4 LDG.128; buffer is short-lived -> low peak regs)
    float tp = 1.0f;
    {
        float4 b0 = xin[segl +   0];
        float4 b1 = xin[segl +  32];
        float4 b2 = xin[segl +  64];
        float4 b3 = xin[segl +  96];
        tp *= ((b0.x * b0.y) * (b0.z * b0.w)) * ((b1.x * b1.y) * (b1.z * b1.w));
        tp *= ((b2.x * b2.y) * (b2.z * b2.w)) * ((b3.x * b3.y) * (b3.z * b3.w));
        b0 = xin[segl + 128];
        b1 = xin[segl + 160];
        b2 = xin[segl + 192];
        b3 = xin[segl + 224];
        tp *= ((b0.x * b0.y) * (b0.z * b0.w)) * ((b1.x * b1.y) * (b1.z * b1.w));
        tp *= ((b2.x * b2.y) * (b2.z * b2.w)) * ((b3.x * b3.y) * (b3.z * b3.w));
    }
    #pragma unroll
    for (int o = 1; o < 32; o <<= 1)
        tp *= __shfl_xor_sync(0xffffffffu, tp, o);
    if (lane == 0) wtot[w] = tp;

    // ---- pass-2 ring prologue BEFORE the barrier (data is L2-resident) ----
    float4 ring[DEPTH];
    #pragma unroll
    for (int k = 0; k < DEPTH; k++)
        ring[k] = __ldcs(&xin[segl + k * 32]);

    __syncthreads();

    // ---- cross-warp exclusive prefix folded into the running carry ----
    float carry = 1.0f;
    #pragma unroll
    for (int ww = 0; ww < NWARPS - 1; ww++) {
        float wt = wtot[ww];
        if (ww < w) carry *= wt;
    }

    // ---- pass 2: reload from L2, scan + scale + store ----
    #pragma unroll
    for (int c = 0; c < CHUNKS; c++) {
        float4 v = ring[c & (DEPTH - 1)];
        if (c + DEPTH < CHUNKS)
            ring[c & (DEPTH - 1)] = __ldcs(&xin[segl + (c + DEPTH) * 32]);

        // local inclusive prefix within the thread's 4 elements
        v.y *= v.x;
        v.z *= v.y;
        v.w *= v.z;

        // warp inclusive scan (product) of per-thread totals
        float s = v.w;
        #pragma unroll
        for (int o = 1; o < 32; o <<= 1) {
            float tv = __shfl_up_sync(0xffffffffu, s, o);
            if (lane >= o) s *= tv;
        }
        float e   = __shfl_up_sync(0xffffffffu, s, 1);
        if (lane == 0) e = 1.0f;
        float tot = __shfl_sync(0xffffffffu, s, 31);

        const float ce = carry * e;   // global exclusive prefix for this thread
        v.x *= ce; v.y *= ce; v.z *= ce; v.w *= ce;
        __stcs(&yout[segl + c * 32], v);

        carry *= tot;
    }
}

extern "C" void kernel_launch(void* const* d_in, const int* in_sizes, int n_in,
                              void* d_out, int out_size) {
    const float* x = (const float*)d_in[0];
    float* y = (float*)d_out;
    const int rows = in_sizes[0] / ROW_LEN;   // 4096
    cumprod_dim1_kernel<<<rows, THREADS>>>(x, y);
}